// round 1
// baseline (speedup 1.0000x reference)
#include <cuda_runtime.h>
#include <cstdint>

// GrahamLoss: per-batch Frobenius distance between Gram matrices.
//   feat, feat_decod: [16, 128, 128, 128] fp32  ->  out: [16] fp32
//
// Strategy: tf32 mma.sync (m16n8k8) GEMM  G = F F^T  per (batch, tensor),
// K-split 8, partials in __device__ scratch, then fused diff^2 reduction.

static constexpr int B_ = 16;
static constexpr int C_ = 128;
static constexpr long N_ = 16384;            // H*W
static constexpr int KSPLIT = 8;
static constexpr int KCHUNK = (int)(N_ / KSPLIT);   // 2048
static constexpr int BK = 32;
static constexpr int NIT = KCHUNK / BK;             // 64
static constexpr int SSTRIDE = 36;  // floats: == 4 (mod 32) -> conflict-free, 16B aligned

// 2 tensors x 16 batches x 8 k-slices x 128x128 fp32 partial grams = 16.8 MiB
__device__ float g_part[2][B_][KSPLIT][C_ * C_];

__global__ void zero_out_kernel(float* out) {
    if (threadIdx.x < B_) out[threadIdx.x] = 0.0f;
}

__device__ __forceinline__ uint32_t f32_to_tf32(float x) {
    uint32_t r;
    asm("cvt.rna.tf32.f32 %0, %1;" : "=r"(r) : "f"(x));
    return r;
}

__global__ __launch_bounds__(256, 1)
void gram_kernel(const float* __restrict__ f_enc, const float* __restrict__ f_dec) {
    const int b  = blockIdx.x;   // batch
    const int g  = blockIdx.y;   // 0 = enc, 1 = dec
    const int ks = blockIdx.z;   // k-slice

    const float* __restrict__ src =
        (g ? f_dec : f_enc) + (size_t)b * C_ * N_ + (size_t)ks * KCHUNK;

    __shared__ float sA[C_ * SSTRIDE];  // [c][k] tile, 128 x 36 floats = 18432 B

    const int tid  = threadIdx.x;
    const int lane = tid & 31;
    const int warp = tid >> 5;
    // 8 warps: 2 (M) x 4 (N). Warp tile 64x32.
    const int mbase = (warp >> 2) * 64;
    const int nbase = (warp & 3) * 32;
    const int gid = lane >> 2;   // group id (0..7)
    const int tig = lane & 3;    // thread-in-group (0..3)

    float acc[4][4][4];
    #pragma unroll
    for (int i = 0; i < 4; i++)
        #pragma unroll
        for (int j = 0; j < 4; j++)
            #pragma unroll
            for (int r = 0; r < 4; r++) acc[i][j][r] = 0.0f;

    // Per-iter global staging: thread t handles float4 id f = t + i*256.
    //   row = f >> 3  (8 float4 per 32-wide k row), kq = (f & 7) * 4
    float4 stage[4];
    #pragma unroll
    for (int i = 0; i < 4; i++) {
        const int f = tid + i * 256;
        const int row = f >> 3;
        const int kq = (f & 7) << 2;
        stage[i] = *(const float4*)(src + (size_t)row * N_ + kq);
    }

    for (int it = 0; it < NIT; ++it) {
        __syncthreads();  // previous iteration's smem reads done
        // Convert to tf32 (round-to-nearest: avoids truncation bias) and store.
        #pragma unroll
        for (int i = 0; i < 4; i++) {
            const int f = tid + i * 256;
            const int row = f >> 3;
            const int kq = (f & 7) << 2;
            float4 w;
            w.x = __uint_as_float(f32_to_tf32(stage[i].x));
            w.y = __uint_as_float(f32_to_tf32(stage[i].y));
            w.z = __uint_as_float(f32_to_tf32(stage[i].z));
            w.w = __uint_as_float(f32_to_tf32(stage[i].w));
            *(float4*)&sA[row * SSTRIDE + kq] = w;
        }
        __syncthreads();  // tile visible

        // Prefetch next tile while computing this one.
        if (it + 1 < NIT) {
            const int k0 = (it + 1) * BK;
            #pragma unroll
            for (int i = 0; i < 4; i++) {
                const int f = tid + i * 256;
                const int row = f >> 3;
                const int kq = (f & 7) << 2;
                stage[i] = *(const float4*)(src + (size_t)row * N_ + k0 + kq);
            }
        }

        #pragma unroll
        for (int k8 = 0; k8 < BK / 8; k8++) {
            const int kb = k8 * 8;
            uint32_t a[4][4];
            #pragma unroll
            for (int am = 0; am < 4; am++) {
                const int r = mbase + am * 16 + gid;
                a[am][0] = __float_as_uint(sA[r * SSTRIDE + kb + tig]);
                a[am][1] = __float_as_uint(sA[(r + 8) * SSTRIDE + kb + tig]);
                a[am][2] = __float_as_uint(sA[r * SSTRIDE + kb + tig + 4]);
                a[am][3] = __float_as_uint(sA[(r + 8) * SSTRIDE + kb + tig + 4]);
            }
            uint32_t bf[4][2];
            #pragma unroll
            for (int bn = 0; bn < 4; bn++) {
                const int cc = nbase + bn * 8 + gid;
                bf[bn][0] = __float_as_uint(sA[cc * SSTRIDE + kb + tig]);
                bf[bn][1] = __float_as_uint(sA[cc * SSTRIDE + kb + tig + 4]);
            }
            #pragma unroll
            for (int am = 0; am < 4; am++) {
                #pragma unroll
                for (int bn = 0; bn < 4; bn++) {
                    asm volatile(
                        "mma.sync.aligned.m16n8k8.row.col.f32.tf32.tf32.f32 "
                        "{%0,%1,%2,%3}, {%4,%5,%6,%7}, {%8,%9}, {%0,%1,%2,%3};\n"
                        : "+f"(acc[am][bn][0]), "+f"(acc[am][bn][1]),
                          "+f"(acc[am][bn][2]), "+f"(acc[am][bn][3])
                        : "r"(a[am][0]), "r"(a[am][1]), "r"(a[am][2]), "r"(a[am][3]),
                          "r"(bf[bn][0]), "r"(bf[bn][1]));
                }
            }
        }
    }

    // Epilogue: write partial gram tile.
    float* __restrict__ dst = g_part[g][b][ks];
    #pragma unroll
    for (int am = 0; am < 4; am++) {
        #pragma unroll
        for (int bn = 0; bn < 4; bn++) {
            const int r = mbase + am * 16 + gid;
            const int cc = nbase + bn * 8 + tig * 2;
            *(float2*)&dst[r * C_ + cc] =
                make_float2(acc[am][bn][0], acc[am][bn][1]);
            *(float2*)&dst[(r + 8) * C_ + cc] =
                make_float2(acc[am][bn][2], acc[am][bn][3]);
        }
    }
}

__global__ __launch_bounds__(256, 1)
void reduce_kernel(float* __restrict__ out) {
    const int b = blockIdx.x;       // batch
    const int s = blockIdx.y;       // slice 0..7 of the 16384 gram entries
    const int tid = threadIdx.x;

    float sum = 0.0f;
    #pragma unroll
    for (int j = 0; j < 2; j++) {
        const int i4 = s * 512 + tid * 2 + j;   // float4 index, 4096 total
        float4 e = make_float4(0.f, 0.f, 0.f, 0.f);
        float4 d = make_float4(0.f, 0.f, 0.f, 0.f);
        #pragma unroll
        for (int ks = 0; ks < KSPLIT; ks++) {
            const float4 pe = *(const float4*)&g_part[0][b][ks][i4 * 4];
            const float4 pd = *(const float4*)&g_part[1][b][ks][i4 * 4];
            e.x += pe.x; e.y += pe.y; e.z += pe.z; e.w += pe.w;
            d.x += pd.x; d.y += pd.y; d.z += pd.z; d.w += pd.w;
        }
        const float dx = d.x - e.x, dy = d.y - e.y, dz = d.z - e.z, dw = d.w - e.w;
        sum += dx * dx + dy * dy + dz * dz + dw * dw;
    }

    __shared__ float red[256];
    red[tid] = sum;
    __syncthreads();
    #pragma unroll
    for (int o = 128; o > 0; o >>= 1) {
        if (tid < o) red[tid] += red[tid + o];
        __syncthreads();
    }
    if (tid == 0) {
        // denom = 4 * N^2 * C^2 = 2^44 (exact in fp32)
        const float scale = 1.0f / (4.0f * (float)N_ * (float)N_ * (float)C_ * (float)C_);
        atomicAdd(out + b, red[0] * scale);
    }
}

extern "C" void kernel_launch(void* const* d_in, const int* in_sizes, int n_in,
                              void* d_out, int out_size) {
    const float* feat = (const float*)d_in[0];
    const float* feat_dec = (const float*)d_in[1];
    float* out = (float*)d_out;

    zero_out_kernel<<<1, 32>>>(out);
    dim3 grid(B_, 2, KSPLIT);
    gram_kernel<<<grid, 256>>>(feat, feat_dec);
    reduce_kernel<<<dim3(B_, KSPLIT), 256>>>(out);
}

// round 2
// speedup vs baseline: 1.1516x; 1.1516x over previous
#include <cuda_runtime.h>
#include <cstdint>

// GrahamLoss: per-batch Frobenius distance between Gram matrices.
//   feat, feat_decod: [16, 128, 128, 128] fp32  ->  out: [16] fp32
//
// tf32 mma.sync (m16n8k8) GEMM G = F F^T per (batch, tensor), K-split 8,
// ldmatrix fragment loads, 2 CTAs/SM (single wave), fused diff^2 reduce.

static constexpr int B_ = 16;
static constexpr int C_ = 128;
static constexpr long N_ = 16384;            // H*W
static constexpr int KSPLIT = 8;
static constexpr int KCHUNK = (int)(N_ / KSPLIT);   // 2048
static constexpr int BK = 32;
static constexpr int NIT = KCHUNK / BK;             // 64
static constexpr int SSTRIDE = 36;  // == 4 (mod 32): conflict-free STS.128 + LDSM

// 2 tensors x 16 batches x 8 k-slices x 128x128 fp32 partial grams = 16.8 MiB
__device__ float g_part[2][B_][KSPLIT][C_ * C_];

__device__ __forceinline__ uint32_t f32_to_tf32(float x) {
    uint32_t r;
    asm("cvt.rna.tf32.f32 %0, %1;" : "=r"(r) : "f"(x));
    return r;
}

__device__ __forceinline__ uint32_t smem_u32(const void* p) {
    return (uint32_t)__cvta_generic_to_shared(p);
}

__global__ __launch_bounds__(256, 2)
void gram_kernel(const float* __restrict__ f_enc, const float* __restrict__ f_dec,
                 float* __restrict__ out) {
    const int b  = blockIdx.x;   // batch
    const int g  = blockIdx.y;   // 0 = enc, 1 = dec
    const int ks = blockIdx.z;   // k-slice

    // Initialize output (safe: reduce_kernel launches after this kernel completes).
    if (g == 0 && ks == 0 && threadIdx.x == 0) out[b] = 0.0f;

    const float* __restrict__ src =
        (g ? f_dec : f_enc) + (size_t)b * C_ * N_ + (size_t)ks * KCHUNK;

    __shared__ float sA[C_ * SSTRIDE];  // [c][k] tile, 128 x 36 floats = 18432 B

    const int tid  = threadIdx.x;
    const int lane = tid & 31;
    const int warp = tid >> 5;
    // 8 warps: 2 (M) x 4 (N). Warp tile 64x32.
    const int mbase = (warp >> 2) * 64;
    const int nbase = (warp & 3) * 32;
    const int gid = lane >> 2;   // group id (0..7)
    const int tig = lane & 3;    // thread-in-group (0..3)

    // ldmatrix lane -> (matrix j, row within matrix)
    const int j  = lane >> 3;
    const int lr = lane & 7;

    // A fragment submatrix bases (am = 0..3):
    //   mat j: row offset (j&1)*8, col offset (j>>1)*4
    uint32_t aaddr[4];
    #pragma unroll
    for (int am = 0; am < 4; am++) {
        const int row = mbase + am * 16 + ((j & 1) << 3) + lr;
        const int col = (j >> 1) << 2;
        aaddr[am] = smem_u32(&sA[row * SSTRIDE + col]);
    }
    // B fragment submatrix bases (pair p covers bn = 2p, 2p+1):
    //   mat j: row offset (j>>1)*8, col offset (j&1)*4
    uint32_t baddr[2];
    #pragma unroll
    for (int p = 0; p < 2; p++) {
        const int row = nbase + p * 16 + ((j >> 1) << 3) + lr;
        const int col = (j & 1) << 2;
        baddr[p] = smem_u32(&sA[row * SSTRIDE + col]);
    }

    float acc[4][4][4];
    #pragma unroll
    for (int i = 0; i < 4; i++)
        #pragma unroll
        for (int jj = 0; jj < 4; jj++)
            #pragma unroll
            for (int r = 0; r < 4; r++) acc[i][jj][r] = 0.0f;

    // Per-iter global staging: thread t handles float4 id f = t + i*256.
    float4 stage[4];
    #pragma unroll
    for (int i = 0; i < 4; i++) {
        const int f = tid + i * 256;
        const int row = f >> 3;
        const int kq = (f & 7) << 2;
        stage[i] = *(const float4*)(src + (size_t)row * N_ + kq);
    }

    for (int it = 0; it < NIT; ++it) {
        __syncthreads();  // previous iteration's smem reads done
        #pragma unroll
        for (int i = 0; i < 4; i++) {
            const int f = tid + i * 256;
            const int row = f >> 3;
            const int kq = (f & 7) << 2;
            float4 w;
            w.x = __uint_as_float(f32_to_tf32(stage[i].x));
            w.y = __uint_as_float(f32_to_tf32(stage[i].y));
            w.z = __uint_as_float(f32_to_tf32(stage[i].z));
            w.w = __uint_as_float(f32_to_tf32(stage[i].w));
            *(float4*)&sA[row * SSTRIDE + kq] = w;
        }
        __syncthreads();  // tile visible

        // Prefetch next tile while computing this one.
        if (it + 1 < NIT) {
            const int k0 = (it + 1) * BK;
            #pragma unroll
            for (int i = 0; i < 4; i++) {
                const int f = tid + i * 256;
                const int row = f >> 3;
                const int kq = (f & 7) << 2;
                stage[i] = *(const float4*)(src + (size_t)row * N_ + k0 + kq);
            }
        }

        #pragma unroll
        for (int k8 = 0; k8 < BK / 8; k8++) {
            const uint32_t koff = (uint32_t)(k8 * 8 * 4);  // kb floats -> bytes

            uint32_t a[4][4];
            #pragma unroll
            for (int am = 0; am < 4; am++) {
                asm volatile(
                    "ldmatrix.sync.aligned.m8n8.x4.shared.b16 {%0,%1,%2,%3}, [%4];"
                    : "=r"(a[am][0]), "=r"(a[am][1]), "=r"(a[am][2]), "=r"(a[am][3])
                    : "r"(aaddr[am] + koff));
            }
            uint32_t bf[2][4];  // [p][{bn0.k0, bn0.k4, bn1.k0, bn1.k4}]
            #pragma unroll
            for (int p = 0; p < 2; p++) {
                asm volatile(
                    "ldmatrix.sync.aligned.m8n8.x4.shared.b16 {%0,%1,%2,%3}, [%4];"
                    : "=r"(bf[p][0]), "=r"(bf[p][1]), "=r"(bf[p][2]), "=r"(bf[p][3])
                    : "r"(baddr[p] + koff));
            }
            #pragma unroll
            for (int am = 0; am < 4; am++) {
                #pragma unroll
                for (int bn = 0; bn < 4; bn++) {
                    const int p = bn >> 1;
                    const int q = (bn & 1) << 1;
                    asm volatile(
                        "mma.sync.aligned.m16n8k8.row.col.f32.tf32.tf32.f32 "
                        "{%0,%1,%2,%3}, {%4,%5,%6,%7}, {%8,%9}, {%0,%1,%2,%3};\n"
                        : "+f"(acc[am][bn][0]), "+f"(acc[am][bn][1]),
                          "+f"(acc[am][bn][2]), "+f"(acc[am][bn][3])
                        : "r"(a[am][0]), "r"(a[am][1]), "r"(a[am][2]), "r"(a[am][3]),
                          "r"(bf[p][q]), "r"(bf[p][q + 1]));
                }
            }
        }
    }

    // Epilogue: write partial gram tile.
    float* __restrict__ dst = g_part[g][b][ks];
    #pragma unroll
    for (int am = 0; am < 4; am++) {
        #pragma unroll
        for (int bn = 0; bn < 4; bn++) {
            const int r = mbase + am * 16 + gid;
            const int cc = nbase + bn * 8 + tig * 2;
            *(float2*)&dst[r * C_ + cc] =
                make_float2(acc[am][bn][0], acc[am][bn][1]);
            *(float2*)&dst[(r + 8) * C_ + cc] =
                make_float2(acc[am][bn][2], acc[am][bn][3]);
        }
    }
}

__global__ __launch_bounds__(256, 1)
void reduce_kernel(float* __restrict__ out) {
    const int b = blockIdx.x;       // batch
    const int s = blockIdx.y;       // slice 0..7 of the 16384 gram entries
    const int tid = threadIdx.x;

    float sum = 0.0f;
    #pragma unroll
    for (int jj = 0; jj < 2; jj++) {
        const int i4 = s * 512 + jj * 256 + tid;   // float4 index, 4096 total
        float4 e = make_float4(0.f, 0.f, 0.f, 0.f);
        float4 d = make_float4(0.f, 0.f, 0.f, 0.f);
        #pragma unroll
        for (int ks = 0; ks < KSPLIT; ks++) {
            const float4 pe = *(const float4*)&g_part[0][b][ks][i4 * 4];
            const float4 pd = *(const float4*)&g_part[1][b][ks][i4 * 4];
            e.x += pe.x; e.y += pe.y; e.z += pe.z; e.w += pe.w;
            d.x += pd.x; d.y += pd.y; d.z += pd.z; d.w += pd.w;
        }
        const float dx = d.x - e.x, dy = d.y - e.y, dz = d.z - e.z, dw = d.w - e.w;
        sum += dx * dx + dy * dy + dz * dz + dw * dw;
    }

    __shared__ float red[256];
    red[tid] = sum;
    __syncthreads();
    #pragma unroll
    for (int o = 128; o > 0; o >>= 1) {
        if (tid < o) red[tid] += red[tid + o];
        __syncthreads();
    }
    if (tid == 0) {
        // denom = 4 * N^2 * C^2 = 2^44 (exact in fp32)
        const float scale = 1.0f / (4.0f * (float)N_ * (float)N_ * (float)C_ * (float)C_);
        atomicAdd(out + b, red[0] * scale);
    }
}

extern "C" void kernel_launch(void* const* d_in, const int* in_sizes, int n_in,
                              void* d_out, int out_size) {
    const float* feat = (const float*)d_in[0];
    const float* feat_dec = (const float*)d_in[1];
    float* out = (float*)d_out;

    dim3 grid(B_, 2, KSPLIT);
    gram_kernel<<<grid, 256>>>(feat, feat_dec, out);
    reduce_kernel<<<dim3(B_, KSPLIT), 256>>>(out);
}

// round 5
// speedup vs baseline: 1.7181x; 1.4919x over previous
#include <cuda_runtime.h>
#include <cuda_fp16.h>
#include <cstdint>

// GrahamLoss: per-batch Frobenius distance between Gram matrices.
//   feat, feat_decod: [16, 128, 128, 128] fp32 -> out: [16] fp32
//
// fp16 mma.sync m16n8k16 (fp32 accum). Each CTA (b, ks) computes the SIGNED
// partial  dec_gram - enc_gram  over a 1024-wide K slice by accumulating enc,
// negating the accumulators, then accumulating dec. Partials summed + squared
// by reduce_kernel.

static constexpr int B_ = 16;
static constexpr int C_ = 128;
static constexpr long N_ = 16384;          // H*W
static constexpr int KS = 16;              // k-slices
static constexpr int KCHUNK = (int)(N_ / KS);   // 1024 per tensor
static constexpr int BK = 64;              // halfs per row per tile (128 B row)
static constexpr int NTILE = 2 * KCHUNK / BK;   // 32 (16 enc + 16 dec)

// 16 batches x 16 k-slices x 128x128 fp32 signed partials = 16.8 MiB
__device__ float g_part[B_][KS][C_ * C_];

__device__ __forceinline__ uint32_t smem_u32(const void* p) {
    return (uint32_t)__cvta_generic_to_shared(p);
}

// Pack two fp32 into f16x2 (round-to-nearest): lo -> lower half, hi -> upper.
__device__ __forceinline__ uint32_t pack_f16x2(float lo, float hi) {
    uint32_t r;
    asm("cvt.rn.f16x2.f32 %0, %1, %2;" : "=r"(r) : "f"(hi), "f"(lo));
    return r;
}

__global__ __launch_bounds__(256, 2)
void gram_kernel(const float* __restrict__ f_enc, const float* __restrict__ f_dec,
                 float* __restrict__ out) {
    const int b  = blockIdx.x;
    const int ks = blockIdx.y;
    const int tid  = threadIdx.x;
    const int lane = tid & 31;
    const int warp = tid >> 5;

    if (ks == 0 && tid == 0) out[b] = 0.0f;

    const float* __restrict__ base_e = f_enc + (size_t)b * C_ * N_ + (size_t)ks * KCHUNK;
    const float* __restrict__ base_d = f_dec + (size_t)b * C_ * N_ + (size_t)ks * KCHUNK;

    __shared__ __align__(1024) __half tile[C_ * BK];   // 16 KB, SW128-xor swizzled

    // 8 warps: 2 (M) x 4 (N); warp tile 64x32.
    const int mbase = (warp >> 2) * 64;
    const int nbase = (warp & 3) * 32;
    const int gid = lane >> 2;   // 0..7
    const int tig = lane & 3;    // 0..3

    // ---- staging / store maps: store id h = tid + s*256 (4 per thread) ----
    //   row = h>>3 (8 stores per 64-half row), col bytes = (h&7)*16
    size_t goff[4];
    uint32_t soff[4];
    #pragma unroll
    for (int s = 0; s < 4; s++) {
        const int h = tid + s * 256;
        const int row = h >> 3;
        const int colb = (h & 7) << 4;
        goff[s] = (size_t)row * N_ + (size_t)((h & 7) << 3);   // floats
        soff[s] = (uint32_t)row * 128u + ((uint32_t)colb ^ (uint32_t)((row & 7) << 4));
    }

    // ---- ldmatrix address precompute ----
    const int j  = lane >> 3;   // matrix id within ldmatrix.x4
    const int lr = lane & 7;    // row within matrix
    const uint32_t tbase = smem_u32(tile);
    uint32_t aAddr[4], aXor[4];
    #pragma unroll
    for (int am = 0; am < 4; am++) {
        const int row = mbase + am * 16 + ((j & 1) << 3) + lr;
        aAddr[am] = tbase + (uint32_t)row * 128u;
        aXor[am]  = (uint32_t)((row & 7) << 4);
    }
    const uint32_t colA = (uint32_t)((j >> 1) << 4);
    uint32_t bAddr[2], bXor[2];
    #pragma unroll
    for (int p = 0; p < 2; p++) {
        const int row = nbase + p * 16 + ((j >> 1) << 3) + lr;
        bAddr[p] = tbase + (uint32_t)row * 128u;
        bXor[p]  = (uint32_t)((row & 7) << 4);
    }
    const uint32_t colB = (uint32_t)((j & 1) << 4);

    float acc[4][4][4];
    #pragma unroll
    for (int i = 0; i < 4; i++)
        #pragma unroll
        for (int jj = 0; jj < 4; jj++)
            #pragma unroll
            for (int r = 0; r < 4; r++) acc[i][jj][r] = 0.0f;

    // ---- register prefetch of tile 0 ----
    float4 st[4][2];
    {
        const float* s0 = base_e;
        #pragma unroll
        for (int s = 0; s < 4; s++) {
            st[s][0] = *(const float4*)(s0 + goff[s]);
            st[s][1] = *(const float4*)(s0 + goff[s] + 4);
        }
    }

    for (int it = 0; it < NTILE; ++it) {
        __syncthreads();  // previous tile's ldmatrix reads done
        #pragma unroll
        for (int s = 0; s < 4; s++) {
            uint4 v;
            v.x = pack_f16x2(st[s][0].x, st[s][0].y);
            v.y = pack_f16x2(st[s][0].z, st[s][0].w);
            v.z = pack_f16x2(st[s][1].x, st[s][1].y);
            v.w = pack_f16x2(st[s][1].z, st[s][1].w);
            *(uint4*)((char*)tile + soff[s]) = v;
        }
        __syncthreads();  // tile visible

        // Prefetch next tile while this one computes.
        if (it + 1 < NTILE) {
            const int nt = it + 1;
            const float* s0 = (nt < KS ? base_e : base_d) + (nt & (KS - 1)) * BK;
            #pragma unroll
            for (int s = 0; s < 4; s++) {
                st[s][0] = *(const float4*)(s0 + goff[s]);
                st[s][1] = *(const float4*)(s0 + goff[s] + 4);
            }
        }

        // Switch from enc to dec: acc <- -acc (so final = dec - enc).
        if (it == KS) {
            #pragma unroll
            for (int i = 0; i < 4; i++)
                #pragma unroll
                for (int jj = 0; jj < 4; jj++)
                    #pragma unroll
                    for (int r = 0; r < 4; r++) acc[i][jj][r] = -acc[i][jj][r];
        }

        #pragma unroll
        for (int k16 = 0; k16 < BK / 16; k16++) {
            const uint32_t kb = (uint32_t)(k16 * 32);   // bytes (16 halfs)

            uint32_t a[4][4];
            #pragma unroll
            for (int am = 0; am < 4; am++) {
                asm volatile(
                    "ldmatrix.sync.aligned.m8n8.x4.shared.b16 {%0,%1,%2,%3}, [%4];"
                    : "=r"(a[am][0]), "=r"(a[am][1]), "=r"(a[am][2]), "=r"(a[am][3])
                    : "r"(aAddr[am] + ((colA + kb) ^ aXor[am])));
            }
            uint32_t bf[2][4];   // [p][{bn0.k0, bn0.k8, bn1.k0, bn1.k8}]
            #pragma unroll
            for (int p = 0; p < 2; p++) {
                asm volatile(
                    "ldmatrix.sync.aligned.m8n8.x4.shared.b16 {%0,%1,%2,%3}, [%4];"
                    : "=r"(bf[p][0]), "=r"(bf[p][1]), "=r"(bf[p][2]), "=r"(bf[p][3])
                    : "r"(bAddr[p] + ((colB + kb) ^ bXor[p])));
            }
            #pragma unroll
            for (int am = 0; am < 4; am++) {
                #pragma unroll
                for (int bn = 0; bn < 4; bn++) {
                    const int p = bn >> 1;
                    const int q = (bn & 1) << 1;
                    asm volatile(
                        "mma.sync.aligned.m16n8k16.row.col.f32.f16.f16.f32 "
                        "{%0,%1,%2,%3}, {%4,%5,%6,%7}, {%8,%9}, {%0,%1,%2,%3};\n"
                        : "+f"(acc[am][bn][0]), "+f"(acc[am][bn][1]),
                          "+f"(acc[am][bn][2]), "+f"(acc[am][bn][3])
                        : "r"(a[am][0]), "r"(a[am][1]), "r"(a[am][2]), "r"(a[am][3]),
                          "r"(bf[p][q]), "r"(bf[p][q + 1]));
                }
            }
        }
    }

    // Epilogue: write signed partial (dec - enc) gram tile.
    float* __restrict__ dst = g_part[b][ks];
    #pragma unroll
    for (int am = 0; am < 4; am++) {
        #pragma unroll
        for (int bn = 0; bn < 4; bn++) {
            const int r = mbase + am * 16 + gid;
            const int cc = nbase + bn * 8 + tig * 2;
            *(float2*)&dst[r * C_ + cc] =
                make_float2(acc[am][bn][0], acc[am][bn][1]);
            *(float2*)&dst[(r + 8) * C_ + cc] =
                make_float2(acc[am][bn][2], acc[am][bn][3]);
        }
    }
}

__global__ __launch_bounds__(256, 1)
void reduce_kernel(float* __restrict__ out) {
    const int b = blockIdx.x;
    const int sl = blockIdx.y;          // 16 slices of 256 float4
    const int tid = threadIdx.x;
    const int i4 = sl * 256 + tid;      // 0..4095

    float4 s = make_float4(0.f, 0.f, 0.f, 0.f);
    #pragma unroll
    for (int ks = 0; ks < KS; ks++) {
        const float4 v = *(const float4*)&g_part[b][ks][i4 * 4];
        s.x += v.x; s.y += v.y; s.z += v.z; s.w += v.w;
    }
    float sum = s.x * s.x + s.y * s.y + s.z * s.z + s.w * s.w;

    __shared__ float red[256];
    red[tid] = sum;
    __syncthreads();
    #pragma unroll
    for (int o = 128; o > 0; o >>= 1) {
        if (tid < o) red[tid] += red[tid + o];
        __syncthreads();
    }
    if (tid == 0) {
        // denom = 4 * N^2 * C^2 = 2^44 (exact in fp32)
        const float scale = 1.0f / (4.0f * (float)N_ * (float)N_ * (float)C_ * (float)C_);
        atomicAdd(out + b, red[0] * scale);
    }
}

extern "C" void kernel_launch(void* const* d_in, const int* in_sizes, int n_in,
                              void* d_out, int out_size) {
    const float* feat = (const float*)d_in[0];
    const float* feat_dec = (const float*)d_in[1];
    float* out = (float*)d_out;

    gram_kernel<<<dim3(B_, KS), 256>>>(feat, feat_dec, out);
    reduce_kernel<<<dim3(B_, KS), 256>>>(out);
}

// round 6
// speedup vs baseline: 1.8390x; 1.0704x over previous
#include <cuda_runtime.h>
#include <cuda_fp16.h>
#include <cstdint>

// GrahamLoss: per-batch Frobenius distance between Gram matrices.
//   feat, feat_decod: [16, 128, 128, 128] fp32 -> out: [16] fp32
//
// fp16 mma.sync m16n8k16 (fp32 accum). Each CTA (b, ks) computes the SIGNED
// partial  dec_gram - enc_gram  over a 1024-wide K slice (enc pass, negate,
// dec pass). Double-buffered smem: one __syncthreads per tile, STS of tile
// t+1 overlaps MMA of tile t. Partials summed + squared by reduce_kernel.

static constexpr int B_ = 16;
static constexpr int C_ = 128;
static constexpr long N_ = 16384;          // H*W
static constexpr int KS = 16;              // k-slices
static constexpr int KCHUNK = (int)(N_ / KS);   // 1024 per tensor
static constexpr int BK = 64;              // halfs per row per tile (128 B row)
static constexpr int NTILE = 2 * KCHUNK / BK;   // 32 (16 enc + 16 dec)
static constexpr int TILE_BYTES = C_ * BK * 2;  // 16384

// 16 batches x 16 k-slices x 128x128 fp32 signed partials = 16.8 MiB
__device__ float g_part[B_][KS][C_ * C_];

__device__ __forceinline__ uint32_t smem_u32(const void* p) {
    return (uint32_t)__cvta_generic_to_shared(p);
}

// Pack two fp32 into f16x2 (round-to-nearest): lo -> lower half, hi -> upper.
__device__ __forceinline__ uint32_t pack_f16x2(float lo, float hi) {
    uint32_t r;
    asm("cvt.rn.f16x2.f32 %0, %1, %2;" : "=r"(r) : "f"(hi), "f"(lo));
    return r;
}

__global__ __launch_bounds__(256, 2)
void gram_kernel(const float* __restrict__ f_enc, const float* __restrict__ f_dec,
                 float* __restrict__ out) {
    const int b  = blockIdx.x;
    const int ks = blockIdx.y;
    const int tid  = threadIdx.x;
    const int lane = tid & 31;
    const int warp = tid >> 5;

    if (ks == 0 && tid == 0) out[b] = 0.0f;

    const float* __restrict__ base_e = f_enc + (size_t)b * C_ * N_ + (size_t)ks * KCHUNK;
    const float* __restrict__ base_d = f_dec + (size_t)b * C_ * N_ + (size_t)ks * KCHUNK;

    __shared__ __align__(1024) __half tile[2][C_ * BK];   // 2 x 16 KB, swizzled

    // 8 warps: 2 (M) x 4 (N); warp tile 64x32.
    const int mbase = (warp >> 2) * 64;
    const int nbase = (warp & 3) * 32;
    const int gid = lane >> 2;   // 0..7
    const int tig = lane & 3;    // 0..3

    // ---- staging / store maps: store id h = tid + s*256 (4 per thread) ----
    //   row = h>>3 (8 stores per 64-half row), col bytes = (h&7)*16
    size_t goff[4];
    uint32_t soff[4];   // byte offset within one buffer (SW128 xor swizzle)
    #pragma unroll
    for (int s = 0; s < 4; s++) {
        const int h = tid + s * 256;
        const int row = h >> 3;
        const int colb = (h & 7) << 4;
        goff[s] = (size_t)row * N_ + (size_t)((h & 7) << 3);   // floats
        soff[s] = (uint32_t)row * 128u + ((uint32_t)colb ^ (uint32_t)((row & 7) << 4));
    }

    // ---- ldmatrix address precompute (buffer 0 base; +TILE_BYTES for buf 1) ----
    const int j  = lane >> 3;   // matrix id within ldmatrix.x4
    const int lr = lane & 7;    // row within matrix
    const uint32_t tbase = smem_u32(&tile[0][0]);
    uint32_t aAddr[4], aXor[4];
    #pragma unroll
    for (int am = 0; am < 4; am++) {
        const int row = mbase + am * 16 + ((j & 1) << 3) + lr;
        aAddr[am] = tbase + (uint32_t)row * 128u;
        aXor[am]  = (uint32_t)((row & 7) << 4);
    }
    const uint32_t colA = (uint32_t)((j >> 1) << 4);
    uint32_t bAddr[2], bXor[2];
    #pragma unroll
    for (int p = 0; p < 2; p++) {
        const int row = nbase + p * 16 + ((j >> 1) << 3) + lr;
        bAddr[p] = tbase + (uint32_t)row * 128u;
        bXor[p]  = (uint32_t)((row & 7) << 4);
    }
    const uint32_t colB = (uint32_t)((j & 1) << 4);

    float acc[4][4][4];
    #pragma unroll
    for (int i = 0; i < 4; i++)
        #pragma unroll
        for (int jj = 0; jj < 4; jj++)
            #pragma unroll
            for (int r = 0; r < 4; r++) acc[i][jj][r] = 0.0f;

    // ---- prologue: load tile 0, store into buffer 0 ----
    float4 st[4][2];
    #pragma unroll
    for (int s = 0; s < 4; s++) {
        st[s][0] = *(const float4*)(base_e + goff[s]);
        st[s][1] = *(const float4*)(base_e + goff[s] + 4);
    }
    #pragma unroll
    for (int s = 0; s < 4; s++) {
        uint4 v;
        v.x = pack_f16x2(st[s][0].x, st[s][0].y);
        v.y = pack_f16x2(st[s][0].z, st[s][0].w);
        v.z = pack_f16x2(st[s][1].x, st[s][1].y);
        v.w = pack_f16x2(st[s][1].z, st[s][1].w);
        *(uint4*)((char*)&tile[0][0] + soff[s]) = v;
    }
    __syncthreads();

    for (int it = 0; it < NTILE; ++it) {
        // Prefetch tile it+1 from global (landed by the time cvt runs below).
        const bool more = (it + 1 < NTILE);
        if (more) {
            const int nt = it + 1;
            const float* s0 = (nt < KS ? base_e : base_d) + (nt & (KS - 1)) * BK;
            #pragma unroll
            for (int s = 0; s < 4; s++) {
                st[s][0] = *(const float4*)(s0 + goff[s]);
                st[s][1] = *(const float4*)(s0 + goff[s] + 4);
            }
        }

        // Switch from enc to dec: acc <- -acc (so final = dec - enc).
        if (it == KS) {
            #pragma unroll
            for (int i = 0; i < 4; i++)
                #pragma unroll
                for (int jj = 0; jj < 4; jj++)
                    #pragma unroll
                    for (int r = 0; r < 4; r++) acc[i][jj][r] = -acc[i][jj][r];
        }

        // Compute tile it from buffer it&1.
        const uint32_t bufo = (uint32_t)(it & 1) * (uint32_t)TILE_BYTES;
        #pragma unroll
        for (int k16 = 0; k16 < BK / 16; k16++) {
            const uint32_t kb = (uint32_t)(k16 * 32);   // bytes (16 halfs)

            uint32_t a[4][4];
            #pragma unroll
            for (int am = 0; am < 4; am++) {
                asm volatile(
                    "ldmatrix.sync.aligned.m8n8.x4.shared.b16 {%0,%1,%2,%3}, [%4];"
                    : "=r"(a[am][0]), "=r"(a[am][1]), "=r"(a[am][2]), "=r"(a[am][3])
                    : "r"(aAddr[am] + bufo + ((colA + kb) ^ aXor[am])));
            }
            uint32_t bf[2][4];   // [p][{bn0.k0, bn0.k8, bn1.k0, bn1.k8}]
            #pragma unroll
            for (int p = 0; p < 2; p++) {
                asm volatile(
                    "ldmatrix.sync.aligned.m8n8.x4.shared.b16 {%0,%1,%2,%3}, [%4];"
                    : "=r"(bf[p][0]), "=r"(bf[p][1]), "=r"(bf[p][2]), "=r"(bf[p][3])
                    : "r"(bAddr[p] + bufo + ((colB + kb) ^ bXor[p])));
            }
            #pragma unroll
            for (int am = 0; am < 4; am++) {
                #pragma unroll
                for (int bn = 0; bn < 4; bn++) {
                    const int p = bn >> 1;
                    const int q = (bn & 1) << 1;
                    asm volatile(
                        "mma.sync.aligned.m16n8k16.row.col.f32.f16.f16.f32 "
                        "{%0,%1,%2,%3}, {%4,%5,%6,%7}, {%8,%9}, {%0,%1,%2,%3};\n"
                        : "+f"(acc[am][bn][0]), "+f"(acc[am][bn][1]),
                          "+f"(acc[am][bn][2]), "+f"(acc[am][bn][3])
                        : "r"(a[am][0]), "r"(a[am][1]), "r"(a[am][2]), "r"(a[am][3]),
                          "r"(bf[p][q]), "r"(bf[p][q + 1]));
                }
            }
        }

        // Store tile it+1 into the other buffer (overlaps with MMA above in
        // the issue stream; safe: that buffer's last readers finished before
        // the previous __syncthreads).
        if (more) {
            char* dstb = (char*)&tile[(it + 1) & 1][0];
            #pragma unroll
            for (int s = 0; s < 4; s++) {
                uint4 v;
                v.x = pack_f16x2(st[s][0].x, st[s][0].y);
                v.y = pack_f16x2(st[s][0].z, st[s][0].w);
                v.z = pack_f16x2(st[s][1].x, st[s][1].y);
                v.w = pack_f16x2(st[s][1].z, st[s][1].w);
                *(uint4*)(dstb + soff[s]) = v;
            }
        }
        __syncthreads();
    }

    // Epilogue: write signed partial (dec - enc) gram tile.
    float* __restrict__ dst = g_part[b][ks];
    #pragma unroll
    for (int am = 0; am < 4; am++) {
        #pragma unroll
        for (int bn = 0; bn < 4; bn++) {
            const int r = mbase + am * 16 + gid;
            const int cc = nbase + bn * 8 + tig * 2;
            *(float2*)&dst[r * C_ + cc] =
                make_float2(acc[am][bn][0], acc[am][bn][1]);
            *(float2*)&dst[(r + 8) * C_ + cc] =
                make_float2(acc[am][bn][2], acc[am][bn][3]);
        }
    }
}

__global__ __launch_bounds__(256, 1)
void reduce_kernel(float* __restrict__ out) {
    const int b = blockIdx.x;
    const int sl = blockIdx.y;          // 16 slices of 256 float4
    const int tid = threadIdx.x;
    const int i4 = sl * 256 + tid;      // 0..4095

    float4 s = make_float4(0.f, 0.f, 0.f, 0.f);
    #pragma unroll
    for (int ks = 0; ks < KS; ks++) {
        const float4 v = *(const float4*)&g_part[b][ks][i4 * 4];
        s.x += v.x; s.y += v.y; s.z += v.z; s.w += v.w;
    }
    float sum = s.x * s.x + s.y * s.y + s.z * s.z + s.w * s.w;

    __shared__ float red[256];
    red[tid] = sum;
    __syncthreads();
    #pragma unroll
    for (int o = 128; o > 0; o >>= 1) {
        if (tid < o) red[tid] += red[tid + o];
        __syncthreads();
    }
    if (tid == 0) {
        // denom = 4 * N^2 * C^2 = 2^44 (exact in fp32)
        const float scale = 1.0f / (4.0f * (float)N_ * (float)N_ * (float)C_ * (float)C_);
        atomicAdd(out + b, red[0] * scale);
    }
}

extern "C" void kernel_launch(void* const* d_in, const int* in_sizes, int n_in,
                              void* d_out, int out_size) {
    const float* feat = (const float*)d_in[0];
    const float* feat_dec = (const float*)d_in[1];
    float* out = (float*)d_out;

    gram_kernel<<<dim3(B_, KS), 256>>>(feat, feat_dec, out);
    reduce_kernel<<<dim3(B_, KS), 256>>>(out);
}

// round 8
// speedup vs baseline: 2.0935x; 1.1384x over previous
#include <cuda_runtime.h>
#include <cuda_fp16.h>
#include <cstdint>

// GrahamLoss: per-batch Frobenius distance between Gram matrices.
//   feat, feat_decod: [16, 128, 128, 128] fp32 -> out: [16] fp32
//
// Symmetric-gram fp16 mma.sync m16n8k16: only the 36 upper-triangular 16x16
// blocks of each 128x128 gram are computed (56% of MACs). Row-band pairs
// (p, 7-p) own 9 tiles each, split 5/4 between two warps (roles). Each CTA
// (b, ks) accumulates the SIGNED partial dec-enc over a 1024-wide K slice.
// reduce_kernel sums partials, squares, weights off-diagonal blocks x2.

static constexpr int B_ = 16;
static constexpr int C_ = 128;
static constexpr long N_ = 16384;            // H*W
static constexpr int KS = 16;                // k-slices
static constexpr int KCHUNK = (int)(N_ / KS);     // 1024 per tensor
static constexpr int BK = 64;                // halfs per row per tile (128 B row)
static constexpr int NTILE = 2 * KCHUNK / BK;     // 32 (16 enc + 16 dec)
static constexpr int TILE_BYTES = C_ * BK * 2;    // 16384
static constexpr int NSYM = 36;              // upper-tri 16x16 blocks

// 16 b x 36 tiles x 16 slices x 256 entries = 9.4 MiB signed partials
__device__ float g_part[B_][NSYM][KS][256];

// ---- symmetric tile bookkeeping (pair p owns tiles t=0..8) ----
__host__ __device__ constexpr int rowOf(int P, int t) {
    return t < 8 - P ? P : 7 - P;
}
__host__ __device__ constexpr int colOf(int P, int t) {
    return t < 8 - P ? P + t : (7 - P) + (t - (8 - P));
}
__host__ __device__ constexpr int cminOf(int P, int T0, int T1) {
    int m = 7;
    for (int t = T0; t < T1; t++) if (colOf(P, t) < m) m = colOf(P, t);
    return m;
}
__host__ __device__ constexpr int cmaxOf(int P, int T0, int T1) {
    int m = 0;
    for (int t = T0; t < T1; t++) if (colOf(P, t) > m) m = colOf(P, t);
    return m;
}

__device__ __forceinline__ uint32_t smem_u32(const void* p) {
    return (uint32_t)__cvta_generic_to_shared(p);
}
__device__ __forceinline__ uint32_t pack_f16x2(float lo, float hi) {
    uint32_t r;
    asm("cvt.rn.f16x2.f32 %0, %1, %2;" : "=r"(r) : "f"(hi), "f"(lo));
    return r;
}
__device__ __forceinline__ void ldsm4(uint32_t r[4], uint32_t addr) {
    asm volatile("ldmatrix.sync.aligned.m8n8.x4.shared.b16 {%0,%1,%2,%3}, [%4];"
                 : "=r"(r[0]), "=r"(r[1]), "=r"(r[2]), "=r"(r[3]) : "r"(addr));
}
__device__ __forceinline__ void mma16816(float* c, const uint32_t a[4],
                                         uint32_t b0, uint32_t b1) {
    asm volatile(
        "mma.sync.aligned.m16n8k16.row.col.f32.f16.f16.f32 "
        "{%0,%1,%2,%3}, {%4,%5,%6,%7}, {%8,%9}, {%0,%1,%2,%3};\n"
        : "+f"(c[0]), "+f"(c[1]), "+f"(c[2]), "+f"(c[3])
        : "r"(a[0]), "r"(a[1]), "r"(a[2]), "r"(a[3]), "r"(b0), "r"(b1));
}

// Compute one BK-wide smem tile's contribution to this warp's output tiles.
template <int P, int ROLE>
__device__ __forceinline__ void compute_tile(float* acc, uint32_t tb, int lane) {
    constexpr int T0 = ROLE ? 5 : 0, T1 = ROLE ? 9 : 5;
    constexpr int C0 = cminOf(P, T0, T1), C1 = cmaxOf(P, T0, T1);
    constexpr int NB = C1 - C0 + 1;
    constexpr bool NA0 = (T0 < 8 - P);   // any tile in row P?
    constexpr bool NA1 = (T1 > 8 - P);   // any tile in row 7-P?

    const int jj = lane >> 3, lr = lane & 7;
    const uint32_t lrx = (uint32_t)lr << 4;
    const uint32_t aRow = ((uint32_t)(jj & 1) << 3) + (uint32_t)lr;
    const uint32_t bRow = ((uint32_t)(jj >> 1) << 3) + (uint32_t)lr;
    const uint32_t aColBase = (uint32_t)(jj >> 1) << 4;
    const uint32_t bColBase = (uint32_t)(jj & 1) << 4;

    #pragma unroll
    for (int k16 = 0; k16 < 4; k16++) {
        const uint32_t cxa = (aColBase | ((uint32_t)k16 << 5)) ^ lrx;
        const uint32_t cxb = (bColBase | ((uint32_t)k16 << 5)) ^ lrx;

        uint32_t a0[4], a1[4];
        if constexpr (NA0) ldsm4(a0, tb + (16u * P + aRow) * 128u + cxa);
        if constexpr (NA1) ldsm4(a1, tb + (16u * (7 - P) + aRow) * 128u + cxa);

        uint32_t bb[NB][4];
        #pragma unroll
        for (int c = 0; c < NB; c++)
            ldsm4(bb[c], tb + (16u * (C0 + c) + bRow) * 128u + cxb);

        #pragma unroll
        for (int t = T0; t < T1; t++) {
            const uint32_t* A;
            if constexpr (NA0 && NA1) A = (rowOf(P, t) == P) ? a0 : a1;
            else if constexpr (NA0)   A = a0;
            else                      A = a1;
            uint32_t* B = bb[colOf(P, t) - C0];
            mma16816(acc + (t - T0) * 8,     A, B[0], B[1]);
            mma16816(acc + (t - T0) * 8 + 4, A, B[2], B[3]);
        }
    }
}

template <int P, int ROLE>
__device__ __forceinline__ void store_tiles(const float* acc, float* gp, int lane) {
    constexpr int T0 = ROLE ? 5 : 0, T1 = ROLE ? 9 : 5;
    const int gid = lane >> 2, tig = lane & 3;
    #pragma unroll
    for (int t = T0; t < T1; t++) {
        float* dst = gp + (P * 9 + t) * (KS * 256);
        const float* a = acc + (t - T0) * 8;
        *(float2*)&dst[gid * 16 + 2 * tig]             = make_float2(a[0], a[1]);
        *(float2*)&dst[(gid + 8) * 16 + 2 * tig]       = make_float2(a[2], a[3]);
        *(float2*)&dst[gid * 16 + 8 + 2 * tig]         = make_float2(a[4], a[5]);
        *(float2*)&dst[(gid + 8) * 16 + 8 + 2 * tig]   = make_float2(a[6], a[7]);
    }
}

#define DISPATCH(FN, ...)                                    \
    switch (code) {                                          \
        case 0: FN<0, 0>(__VA_ARGS__); break;                \
        case 1: FN<0, 1>(__VA_ARGS__); break;                \
        case 2: FN<1, 0>(__VA_ARGS__); break;                \
        case 3: FN<1, 1>(__VA_ARGS__); break;                \
        case 4: FN<2, 0>(__VA_ARGS__); break;                \
        case 5: FN<2, 1>(__VA_ARGS__); break;                \
        case 6: FN<3, 0>(__VA_ARGS__); break;                \
        case 7: FN<3, 1>(__VA_ARGS__); break;                \
    }

__global__ __launch_bounds__(256, 2)
void gram_kernel(const float* __restrict__ f_enc, const float* __restrict__ f_dec,
                 float* __restrict__ out) {
    const int b  = blockIdx.x;
    const int ks = blockIdx.y;
    const int tid  = threadIdx.x;
    const int lane = tid & 31;
    const int warp = tid >> 5;

    if (ks == 0 && tid == 0) out[b] = 0.0f;

    const float* __restrict__ base_e = f_enc + (size_t)b * C_ * N_ + (size_t)ks * KCHUNK;
    const float* __restrict__ base_d = f_dec + (size_t)b * C_ * N_ + (size_t)ks * KCHUNK;

    __shared__ __align__(1024) __half tile[2][C_ * BK];   // 2 x 16 KB, swizzled

    const int pairP = warp >> 1;
    const int role  = ((warp >> 2) ^ warp) & 1;   // balances HMMA across SMSPs
    const int code  = (pairP << 1) | role;

    // ---- staging maps: store id h = tid + s*256 (4 uint4 stores/thread) ----
    size_t goff[4];
    uint32_t soff[4];
    #pragma unroll
    for (int s = 0; s < 4; s++) {
        const int h = tid + s * 256;
        const int row = h >> 3;
        const int colb = (h & 7) << 4;
        goff[s] = (size_t)row * N_ + (size_t)((h & 7) << 3);   // floats
        soff[s] = (uint32_t)row * 128u + ((uint32_t)colb ^ (uint32_t)((row & 7) << 4));
    }
    const uint32_t tbase = smem_u32(&tile[0][0]);

    float acc[40];
    #pragma unroll
    for (int i = 0; i < 40; i++) acc[i] = 0.0f;

    // ---- prologue: tile 0 into buffer 0 ----
    float4 st[4][2];
    #pragma unroll
    for (int s = 0; s < 4; s++) {
        st[s][0] = *(const float4*)(base_e + goff[s]);
        st[s][1] = *(const float4*)(base_e + goff[s] + 4);
    }
    #pragma unroll
    for (int s = 0; s < 4; s++) {
        uint4 v;
        v.x = pack_f16x2(st[s][0].x, st[s][0].y);
        v.y = pack_f16x2(st[s][0].z, st[s][0].w);
        v.z = pack_f16x2(st[s][1].x, st[s][1].y);
        v.w = pack_f16x2(st[s][1].z, st[s][1].w);
        *(uint4*)((char*)&tile[0][0] + soff[s]) = v;
    }
    __syncthreads();

    for (int it = 0; it < NTILE; ++it) {
        const bool more = (it + 1 < NTILE);
        if (more) {
            const int nt = it + 1;
            const float* s0 = (nt < KS ? base_e : base_d) + (nt & (KS - 1)) * BK;
            #pragma unroll
            for (int s = 0; s < 4; s++) {
                st[s][0] = *(const float4*)(s0 + goff[s]);
                st[s][1] = *(const float4*)(s0 + goff[s] + 4);
            }
        }

        // Switch from enc to dec: acc <- -acc (so final = dec - enc).
        if (it == KS) {
            #pragma unroll
            for (int i = 0; i < 40; i++) acc[i] = -acc[i];
        }

        const uint32_t tb = tbase + (uint32_t)(it & 1) * (uint32_t)TILE_BYTES;
        DISPATCH(compute_tile, acc, tb, lane);

        if (more) {
            char* dstb = (char*)&tile[(it + 1) & 1][0];
            #pragma unroll
            for (int s = 0; s < 4; s++) {
                uint4 v;
                v.x = pack_f16x2(st[s][0].x, st[s][0].y);
                v.y = pack_f16x2(st[s][0].z, st[s][0].w);
                v.z = pack_f16x2(st[s][1].x, st[s][1].y);
                v.w = pack_f16x2(st[s][1].z, st[s][1].w);
                *(uint4*)(dstb + soff[s]) = v;
            }
        }
        __syncthreads();
    }

    // Epilogue: write this warp's signed partial tiles.
    float* gp = &g_part[b][0][ks][0];
    DISPATCH(store_tiles, acc, gp, lane);
}

__global__ __launch_bounds__(256, 1)
void reduce_kernel(float* __restrict__ out) {
    const int b = blockIdx.x;
    const int f = blockIdx.y;            // flat symmetric tile 0..35
    const int tid = threadIdx.x;
    const int P = f / 9;
    const int t = f % 9;
    const float w = (t == 0 || t == 8 - P) ? 1.0f : 2.0f;   // diag blocks x1

    float s = 0.0f;
    #pragma unroll
    for (int sl = 0; sl < KS; sl++) s += g_part[b][f][sl][tid];
    float v = w * s * s;

    __shared__ float red[256];
    red[tid] = v;
    __syncthreads();
    #pragma unroll
    for (int o = 128; o > 0; o >>= 1) {
        if (tid < o) red[tid] += red[tid + o];
        __syncthreads();
    }
    if (tid == 0) {
        // denom = 4 * N^2 * C^2 = 2^44 (exact in fp32)
        const float scale = 1.0f / (4.0f * (float)N_ * (float)N_ * (float)C_ * (float)C_);
        atomicAdd(out + b, red[0] * scale);
    }
}

extern "C" void kernel_launch(void* const* d_in, const int* in_sizes, int n_in,
                              void* d_out, int out_size) {
    const float* feat = (const float*)d_in[0];
    const float* feat_dec = (const float*)d_in[1];
    float* out = (float*)d_out;

    gram_kernel<<<dim3(B_, KS), 256>>>(feat, feat_dec, out);
    reduce_kernel<<<dim3(B_, NSYM), 256>>>(out);
}

// round 9
// speedup vs baseline: 2.1857x; 1.0441x over previous
#include <cuda_runtime.h>
#include <cuda_fp16.h>
#include <cstdint>

// GrahamLoss: per-batch Frobenius distance between Gram matrices.
//   feat, feat_decod: [16, 128, 128, 128] fp32 -> out: [16] fp32
//
// Symmetric-gram fp16 mma.sync m16n8k16 (36 upper-tri 16x16 blocks, 56% of
// MACs). Flat balanced work distribution: 296 CTAs (one full 2-CTA/SM wave),
// each owns ~13.8 units (unit = 64-col k-chunk of one batch, enc+dec pass
// with negate-between => signed partial dec-enc). Partials go to slot-indexed
// scratch; loss_kernel recomputes the slot mapping, sums, squares, weights.

static constexpr int B_ = 16;
static constexpr int C_ = 128;
static constexpr long N_ = 16384;            // H*W
static constexpr int BK = 64;                // float cols per unit/tile
static constexpr int TILE_BYTES = C_ * BK * 2;    // 16384 (fp16 tile)
static constexpr int NSYM = 36;              // upper-tri 16x16 blocks
static constexpr int NCTA = 296;             // 2 CTAs x 148 SMs
static constexpr int UNITS = 4096;           // 16 b x 256 chunks
static constexpr int SLOTS = 22;             // max CTAs touching one batch

// 16 x 36 x 22 x 256 x 4B = 13.0 MiB signed partials
__device__ float g_part[B_][NSYM][SLOTS][256];

// ---- symmetric tile bookkeeping (pair p owns tiles t=0..8) ----
__host__ __device__ constexpr int rowOf(int P, int t) {
    return t < 8 - P ? P : 7 - P;
}
__host__ __device__ constexpr int colOf(int P, int t) {
    return t < 8 - P ? P + t : (7 - P) + (t - (8 - P));
}
__host__ __device__ constexpr int cminOf(int P, int T0, int T1) {
    int m = 7;
    for (int t = T0; t < T1; t++) if (colOf(P, t) < m) m = colOf(P, t);
    return m;
}
__host__ __device__ constexpr int cmaxOf(int P, int T0, int T1) {
    int m = 0;
    for (int t = T0; t < T1; t++) if (colOf(P, t) > m) m = colOf(P, t);
    return m;
}

__device__ __forceinline__ uint32_t smem_u32(const void* p) {
    return (uint32_t)__cvta_generic_to_shared(p);
}
__device__ __forceinline__ uint32_t pack_f16x2(float lo, float hi) {
    uint32_t r;
    asm("cvt.rn.f16x2.f32 %0, %1, %2;" : "=r"(r) : "f"(hi), "f"(lo));
    return r;
}
__device__ __forceinline__ void ldsm4(uint32_t r[4], uint32_t addr) {
    asm volatile("ldmatrix.sync.aligned.m8n8.x4.shared.b16 {%0,%1,%2,%3}, [%4];"
                 : "=r"(r[0]), "=r"(r[1]), "=r"(r[2]), "=r"(r[3]) : "r"(addr));
}
__device__ __forceinline__ void mma16816(float* c, const uint32_t a[4],
                                         uint32_t b0, uint32_t b1) {
    asm volatile(
        "mma.sync.aligned.m16n8k16.row.col.f32.f16.f16.f32 "
        "{%0,%1,%2,%3}, {%4,%5,%6,%7}, {%8,%9}, {%0,%1,%2,%3};\n"
        : "+f"(c[0]), "+f"(c[1]), "+f"(c[2]), "+f"(c[3])
        : "r"(a[0]), "r"(a[1]), "r"(a[2]), "r"(a[3]), "r"(b0), "r"(b1));
}

// Compute one BK-wide smem tile's contribution to this warp's output tiles.
template <int P, int ROLE>
__device__ __forceinline__ void compute_tile(float* acc, uint32_t tb, int lane) {
    constexpr int T0 = ROLE ? 5 : 0, T1 = ROLE ? 9 : 5;
    constexpr int C0 = cminOf(P, T0, T1), C1 = cmaxOf(P, T0, T1);
    constexpr int NB = C1 - C0 + 1;
    constexpr bool NA0 = (T0 < 8 - P);   // any tile in row P?
    constexpr bool NA1 = (T1 > 8 - P);   // any tile in row 7-P?

    const int jj = lane >> 3, lr = lane & 7;
    const uint32_t lrx = (uint32_t)lr << 4;
    const uint32_t aRow = ((uint32_t)(jj & 1) << 3) + (uint32_t)lr;
    const uint32_t bRow = ((uint32_t)(jj >> 1) << 3) + (uint32_t)lr;
    const uint32_t aColBase = (uint32_t)(jj >> 1) << 4;
    const uint32_t bColBase = (uint32_t)(jj & 1) << 4;

    #pragma unroll
    for (int k16 = 0; k16 < 4; k16++) {
        const uint32_t cxa = (aColBase | ((uint32_t)k16 << 5)) ^ lrx;
        const uint32_t cxb = (bColBase | ((uint32_t)k16 << 5)) ^ lrx;

        uint32_t a0[4], a1[4];
        if constexpr (NA0) ldsm4(a0, tb + (16u * P + aRow) * 128u + cxa);
        if constexpr (NA1) ldsm4(a1, tb + (16u * (7 - P) + aRow) * 128u + cxa);

        uint32_t bb[NB][4];
        #pragma unroll
        for (int c = 0; c < NB; c++)
            ldsm4(bb[c], tb + (16u * (C0 + c) + bRow) * 128u + cxb);

        #pragma unroll
        for (int t = T0; t < T1; t++) {
            const uint32_t* A;
            if constexpr (NA0 && NA1) A = (rowOf(P, t) == P) ? a0 : a1;
            else if constexpr (NA0)   A = a0;
            else                      A = a1;
            uint32_t* B = bb[colOf(P, t) - C0];
            mma16816(acc + (t - T0) * 8,     A, B[0], B[1]);
            mma16816(acc + (t - T0) * 8 + 4, A, B[2], B[3]);
        }
    }
}

// Store this warp's signed partial tiles; f-stride is SLOTS*256.
template <int P, int ROLE>
__device__ __forceinline__ void store_tiles(const float* acc, float* gp, int lane) {
    constexpr int T0 = ROLE ? 5 : 0, T1 = ROLE ? 9 : 5;
    const int gid = lane >> 2, tig = lane & 3;
    #pragma unroll
    for (int t = T0; t < T1; t++) {
        float* dst = gp + (P * 9 + t) * (SLOTS * 256);
        const float* a = acc + (t - T0) * 8;
        *(float2*)&dst[gid * 16 + 2 * tig]             = make_float2(a[0], a[1]);
        *(float2*)&dst[(gid + 8) * 16 + 2 * tig]       = make_float2(a[2], a[3]);
        *(float2*)&dst[gid * 16 + 8 + 2 * tig]         = make_float2(a[4], a[5]);
        *(float2*)&dst[(gid + 8) * 16 + 8 + 2 * tig]   = make_float2(a[6], a[7]);
    }
}

#define DISPATCH(FN, ...)                                    \
    switch (code) {                                          \
        case 0: FN<0, 0>(__VA_ARGS__); break;                \
        case 1: FN<0, 1>(__VA_ARGS__); break;                \
        case 2: FN<1, 0>(__VA_ARGS__); break;                \
        case 3: FN<1, 1>(__VA_ARGS__); break;                \
        case 4: FN<2, 0>(__VA_ARGS__); break;                \
        case 5: FN<2, 1>(__VA_ARGS__); break;                \
        case 6: FN<3, 0>(__VA_ARGS__); break;                \
        case 7: FN<3, 1>(__VA_ARGS__); break;                \
    }

// One contiguous k-range of one batch: enc pass, negate, dec pass, store.
__device__ __forceinline__ void do_segment(
    const float* __restrict__ base_e, const float* __restrict__ base_d,
    int nt, float* __restrict__ gp, int code, int lane,
    const size_t* goff, const uint32_t* soff, uint32_t tbase, __half* tile0)
{
    float acc[40];
    #pragma unroll
    for (int i = 0; i < 40; i++) acc[i] = 0.0f;

    const int ntot = 2 * nt;

    float4 st[4][2];
    #pragma unroll
    for (int s = 0; s < 4; s++) {
        st[s][0] = *(const float4*)(base_e + goff[s]);
        st[s][1] = *(const float4*)(base_e + goff[s] + 4);
    }
    #pragma unroll
    for (int s = 0; s < 4; s++) {
        uint4 v;
        v.x = pack_f16x2(st[s][0].x, st[s][0].y);
        v.y = pack_f16x2(st[s][0].z, st[s][0].w);
        v.z = pack_f16x2(st[s][1].x, st[s][1].y);
        v.w = pack_f16x2(st[s][1].z, st[s][1].w);
        *(uint4*)((char*)tile0 + soff[s]) = v;
    }
    __syncthreads();

    for (int it = 0; it < ntot; ++it) {
        const bool more = (it + 1 < ntot);
        if (more) {
            const int nt2 = it + 1;
            const float* s0 = (nt2 < nt) ? (base_e + (size_t)nt2 * BK)
                                         : (base_d + (size_t)(nt2 - nt) * BK);
            #pragma unroll
            for (int s = 0; s < 4; s++) {
                st[s][0] = *(const float4*)(s0 + goff[s]);
                st[s][1] = *(const float4*)(s0 + goff[s] + 4);
            }
        }

        if (it == nt) {   // switch enc -> dec: final = dec - enc
            #pragma unroll
            for (int i = 0; i < 40; i++) acc[i] = -acc[i];
        }

        const uint32_t tb = tbase + (uint32_t)(it & 1) * (uint32_t)TILE_BYTES;
        DISPATCH(compute_tile, acc, tb, lane);

        if (more) {
            char* dstb = (char*)tile0 + ((it + 1) & 1) * TILE_BYTES;
            #pragma unroll
            for (int s = 0; s < 4; s++) {
                uint4 v;
                v.x = pack_f16x2(st[s][0].x, st[s][0].y);
                v.y = pack_f16x2(st[s][0].z, st[s][0].w);
                v.z = pack_f16x2(st[s][1].x, st[s][1].y);
                v.w = pack_f16x2(st[s][1].z, st[s][1].w);
                *(uint4*)(dstb + soff[s]) = v;
            }
        }
        __syncthreads();
    }

    DISPATCH(store_tiles, acc, gp, lane);
}

__global__ __launch_bounds__(256, 2)
void gram_kernel(const float* __restrict__ f_enc, const float* __restrict__ f_dec,
                 float* __restrict__ out) {
    const int cta  = blockIdx.x;
    const int tid  = threadIdx.x;
    const int lane = tid & 31;
    const int warp = tid >> 5;

    if (cta == 0 && tid < B_) out[tid] = 0.0f;

    __shared__ __align__(1024) __half tile[2][C_ * BK];   // 2 x 16 KB, swizzled

    const int pairP = warp >> 1;
    const int role  = ((warp >> 2) ^ warp) & 1;   // balances HMMA across SMSPs
    const int code  = (pairP << 1) | role;

    // staging maps: store id h = tid + s*256 (4 uint4 stores/thread)
    size_t goff[4];
    uint32_t soff[4];
    #pragma unroll
    for (int s = 0; s < 4; s++) {
        const int h = tid + s * 256;
        const int row = h >> 3;
        const int colb = (h & 7) << 4;
        goff[s] = (size_t)row * N_ + (size_t)((h & 7) << 3);   // floats
        soff[s] = (uint32_t)row * 128u + ((uint32_t)colb ^ (uint32_t)((row & 7) << 4));
    }
    const uint32_t tbase = smem_u32(&tile[0][0]);

    // Flat unit range for this CTA (unit = 64-col chunk of one batch).
    const int u0 = (cta * UNITS) / NCTA;
    const int u1 = ((cta + 1) * UNITS) / NCTA;
    const int b0 = u0 >> 8;
    const int b1 = (u1 - 1) >> 8;

    {
        const int uend = (b1 > b0) ? ((b0 + 1) << 8) : u1;
        const int kc0  = u0 & 255;
        const size_t off = (size_t)b0 * C_ * N_ + (size_t)kc0 * BK;
        const int slot = cta - ((b0 * NCTA) >> 4);
        do_segment(f_enc + off, f_dec + off, uend - u0,
                   &g_part[b0][0][slot][0], code, lane, goff, soff, tbase,
                   &tile[0][0]);
    }
    if (b1 > b0) {
        const size_t off = (size_t)b1 * C_ * N_;
        const int slot = cta - ((b1 * NCTA) >> 4);
        do_segment(f_enc + off, f_dec + off, u1 - (b1 << 8),
                   &g_part[b1][0][slot][0], code, lane, goff, soff, tbase,
                   &tile[0][0]);
    }
}

__global__ __launch_bounds__(256, 1)
void loss_kernel(float* __restrict__ out) {
    const int b  = blockIdx.x;
    const int fg = blockIdx.y;       // 6 groups of 6 symmetric tiles
    const int tid = threadIdx.x;

    // Which slots are valid for this batch (same mapping as gram_kernel).
    __shared__ int valid[SLOTS];
    if (tid < SLOTS) {
        const int cta = ((b * NCTA) >> 4) + tid;
        int ok = 0;
        if (cta < NCTA) {
            const int u0 = (cta * UNITS) / NCTA;
            const int u1 = ((cta + 1) * UNITS) / NCTA;
            ok = (u0 < (b + 1) * 256) && (u1 > b * 256);
        }
        valid[tid] = ok;
    }
    __syncthreads();

    float sum = 0.0f;
    #pragma unroll
    for (int ff = 0; ff < 6; ff++) {
        const int f = fg * 6 + ff;
        const int P = f / 9;
        const int t = f % 9;
        const float w = (t == 0 || t == 8 - P) ? 1.0f : 2.0f;   // diag x1
        float s = 0.0f;
        for (int sl = 0; sl < SLOTS; sl++)
            if (valid[sl]) s += g_part[b][f][sl][tid];
        sum += w * s * s;
    }

    __shared__ float red[256];
    red[tid] = sum;
    __syncthreads();
    #pragma unroll
    for (int o = 128; o > 0; o >>= 1) {
        if (tid < o) red[tid] += red[tid + o];
        __syncthreads();
    }
    if (tid == 0) {
        // denom = 4 * N^2 * C^2 = 2^44 (exact in fp32)
        const float scale = 1.0f / (4.0f * (float)N_ * (float)N_ * (float)C_ * (float)C_);
        atomicAdd(out + b, red[0] * scale);
    }
}

extern "C" void kernel_launch(void* const* d_in, const int* in_sizes, int n_in,
                              void* d_out, int out_size) {
    const float* feat = (const float*)d_in[0];
    const float* feat_dec = (const float*)d_in[1];
    float* out = (float*)d_out;

    gram_kernel<<<NCTA, 256>>>(feat, feat_dec, out);
    loss_kernel<<<dim3(B_, 6), 256>>>(out);
}